// round 1
// baseline (speedup 1.0000x reference)
#include <cuda_runtime.h>
#include <cuda_bf16.h>

// Problem: out = f(x[32768,1024]) with
//   h  = x@W0 + b0            (1024 -> 128)
//   h  = rmsnorm(h)           (eps=1e-6, no scale)
//   h  = sigmoid(h@W1+b1) + h
//   out= relu(h@W2+b2) + h
//
// Fully fused: one CTA handles 64 rows. Main GEMM is shared-tiled fp32 FFMA
// (BM=64, BN=128(full), BK=32), 4x8 register microtile per thread.
// h tile (64x128) stays in shared; W1/W2 loaded into a reused 64KB shared
// buffer for the two small GEMMs. RMSNorm via 16-lane shuffle reduction
// (each row's 128 cols are owned by exactly one half-warp).

#define BM 64
#define BK 32
#define HD 128      // hidden dim
#define DIN 1024    // input dim
#define AS_STRIDE 36    // padded stride for A tile (bank-conflict-free, float4-aligned)
#define HS_STRIDE 132   // padded stride for h tile

#define HS_FLOATS (BM * HS_STRIDE)        // 8448
#define BUF_FLOATS (HD * HD)              // 16384 (W1/W2), also holds As+Bs in phase A
#define SMEM_FLOATS (HS_FLOATS + BUF_FLOATS)
#define SMEM_BYTES (SMEM_FLOATS * 4)      // 99328 bytes

__global__ __launch_bounds__(256, 2)
void fused_mlp_kernel(const float* __restrict__ x,
                      const float* __restrict__ W0,
                      const float* __restrict__ b0,
                      const float* __restrict__ W1,
                      const float* __restrict__ b1,
                      const float* __restrict__ W2,
                      const float* __restrict__ b2,
                      float* __restrict__ out)
{
    extern __shared__ float smem[];
    float* h_s = smem;                 // [64][HS_STRIDE]
    float* buf = smem + HS_FLOATS;     // phase A: As(64x36)+Bs(32x128); phase B/C: W (128x128)
    float* As = buf;                   // stride AS_STRIDE
    float* Bs = buf + BM * AS_STRIDE;  // 2304 floats in; [32][128]

    const int tid = threadIdx.x;
    const int tx = tid & 15;           // 0..15 -> col group (8 cols each)
    const int ty = tid >> 4;           // 0..15 -> row group (4 rows each)
    const int m0 = blockIdx.x * BM;

    float acc[4][8];
    #pragma unroll
    for (int r = 0; r < 4; r++)
        #pragma unroll
        for (int c = 0; c < 8; c++) acc[r][c] = 0.f;

    // ---- Phase A: GEMM0 = x[m0:m0+64, :] @ W0 -------------------------------
    const int la_row = tid >> 2;          // 0..63
    const int la_col = (tid & 3) * 8;     // 0,8,16,24
    const int lb_row = tid >> 3;          // 0..31
    const int lb_col = (tid & 7) * 16;    // 0..112

    const float* xg_base = x + (size_t)(m0 + la_row) * DIN + la_col;
    const float* wg_base = W0 + (size_t)lb_row * HD + lb_col;

    for (int k0 = 0; k0 < DIN; k0 += BK) {
        // load A tile: 64x32 of x
        const float4* xg = reinterpret_cast<const float4*>(xg_base + k0);
        float4 a0 = xg[0];
        float4 a1 = xg[1];
        *reinterpret_cast<float4*>(&As[la_row * AS_STRIDE + la_col])     = a0;
        *reinterpret_cast<float4*>(&As[la_row * AS_STRIDE + la_col + 4]) = a1;
        // load B tile: 32x128 of W0
        const float4* wg = reinterpret_cast<const float4*>(wg_base + (size_t)k0 * HD);
        float4 w0v = wg[0], w1v = wg[1], w2v = wg[2], w3v = wg[3];
        float4* bsp = reinterpret_cast<float4*>(&Bs[lb_row * HD + lb_col]);
        bsp[0] = w0v; bsp[1] = w1v; bsp[2] = w2v; bsp[3] = w3v;
        __syncthreads();

        #pragma unroll
        for (int kk = 0; kk < BK; kk++) {
            float a[4];
            #pragma unroll
            for (int r = 0; r < 4; r++)
                a[r] = As[(ty * 4 + r) * AS_STRIDE + kk];
            float4 blo = *reinterpret_cast<const float4*>(&Bs[kk * HD + tx * 8]);
            float4 bhi = *reinterpret_cast<const float4*>(&Bs[kk * HD + tx * 8 + 4]);
            float b[8] = {blo.x, blo.y, blo.z, blo.w, bhi.x, bhi.y, bhi.z, bhi.w};
            #pragma unroll
            for (int r = 0; r < 4; r++)
                #pragma unroll
                for (int c = 0; c < 8; c++)
                    acc[r][c] = fmaf(a[r], b[c], acc[r][c]);
        }
        __syncthreads();
    }

    // ---- bias + RMSNorm -----------------------------------------------------
    #pragma unroll
    for (int c = 0; c < 8; c++) {
        float bb = b0[tx * 8 + c];
        #pragma unroll
        for (int r = 0; r < 4; r++) acc[r][c] += bb;
    }
    // each row's 128 cols are owned by the 16 threads sharing ty (one half-warp)
    #pragma unroll
    for (int r = 0; r < 4; r++) {
        float ss = 0.f;
        #pragma unroll
        for (int c = 0; c < 8; c++) ss = fmaf(acc[r][c], acc[r][c], ss);
        #pragma unroll
        for (int m = 8; m > 0; m >>= 1)
            ss += __shfl_xor_sync(0xffffffffu, ss, m, 16);
        float scale = rsqrtf(ss * (1.0f / 128.0f) + 1e-6f);
        #pragma unroll
        for (int c = 0; c < 8; c++) {
            acc[r][c] *= scale;                                   // acc now = rmsnorm(h)
            h_s[(ty * 4 + r) * HS_STRIDE + tx * 8 + c] = acc[r][c];
        }
    }

    // ---- load W1 into buf ---------------------------------------------------
    {
        const float4* wg = reinterpret_cast<const float4*>(W1);
        float4* bp = reinterpret_cast<float4*>(buf);
        #pragma unroll
        for (int i = 0; i < 16; i++) bp[tid + i * 256] = wg[tid + i * 256];
    }
    __syncthreads();

    // ---- GEMM1: z = h @ W1 --------------------------------------------------
    float acc2[4][8];
    #pragma unroll
    for (int r = 0; r < 4; r++)
        #pragma unroll
        for (int c = 0; c < 8; c++) acc2[r][c] = 0.f;

    #pragma unroll 4
    for (int k = 0; k < HD; k++) {
        float a[4];
        #pragma unroll
        for (int r = 0; r < 4; r++)
            a[r] = h_s[(ty * 4 + r) * HS_STRIDE + k];
        float4 blo = *reinterpret_cast<const float4*>(&buf[k * HD + tx * 8]);
        float4 bhi = *reinterpret_cast<const float4*>(&buf[k * HD + tx * 8 + 4]);
        float b[8] = {blo.x, blo.y, blo.z, blo.w, bhi.x, bhi.y, bhi.z, bhi.w};
        #pragma unroll
        for (int r = 0; r < 4; r++)
            #pragma unroll
            for (int c = 0; c < 8; c++)
                acc2[r][c] = fmaf(a[r], b[c], acc2[r][c]);
    }
    __syncthreads();   // all reads of h_s and buf (W1) done

    // ---- sigmoid + residual; write h1 back to h_s ---------------------------
    #pragma unroll
    for (int c = 0; c < 8; c++) {
        float bb = b1[tx * 8 + c];
        #pragma unroll
        for (int r = 0; r < 4; r++) {
            float z = acc2[r][c] + bb;
            float h1 = 1.f / (1.f + __expf(-z)) + acc[r][c];  // residual from registers
            acc[r][c] = h1;                                    // acc now = h1
            h_s[(ty * 4 + r) * HS_STRIDE + tx * 8 + c] = h1;
        }
    }

    // ---- load W2 into buf ---------------------------------------------------
    {
        const float4* wg = reinterpret_cast<const float4*>(W2);
        float4* bp = reinterpret_cast<float4*>(buf);
        #pragma unroll
        for (int i = 0; i < 16; i++) bp[tid + i * 256] = wg[tid + i * 256];
    }
    __syncthreads();

    // ---- GEMM2: z = h1 @ W2 -------------------------------------------------
    #pragma unroll
    for (int r = 0; r < 4; r++)
        #pragma unroll
        for (int c = 0; c < 8; c++) acc2[r][c] = 0.f;

    #pragma unroll 4
    for (int k = 0; k < HD; k++) {
        float a[4];
        #pragma unroll
        for (int r = 0; r < 4; r++)
            a[r] = h_s[(ty * 4 + r) * HS_STRIDE + k];
        float4 blo = *reinterpret_cast<const float4*>(&buf[k * HD + tx * 8]);
        float4 bhi = *reinterpret_cast<const float4*>(&buf[k * HD + tx * 8 + 4]);
        float b[8] = {blo.x, blo.y, blo.z, blo.w, bhi.x, bhi.y, bhi.z, bhi.w};
        #pragma unroll
        for (int r = 0; r < 4; r++)
            #pragma unroll
            for (int c = 0; c < 8; c++)
                acc2[r][c] = fmaf(a[r], b[c], acc2[r][c]);
    }

    // ---- relu + residual; write output --------------------------------------
    #pragma unroll
    for (int r = 0; r < 4; r++) {
        float4 o[2];
        float* of = reinterpret_cast<float*>(o);
        #pragma unroll
        for (int c = 0; c < 8; c++) {
            float z = acc2[r][c] + b2[tx * 8 + c];
            of[c] = fmaxf(z, 0.f) + acc[r][c];   // residual h1 from registers
        }
        float4* og = reinterpret_cast<float4*>(out + (size_t)(m0 + ty * 4 + r) * HD + tx * 8);
        og[0] = o[0];
        og[1] = o[1];
    }
}

extern "C" void kernel_launch(void* const* d_in, const int* in_sizes, int n_in,
                              void* d_out, int out_size)
{
    const float* x  = (const float*)d_in[0];
    const float* W0 = (const float*)d_in[1];
    const float* b0 = (const float*)d_in[2];
    const float* W1 = (const float*)d_in[3];
    const float* b1 = (const float*)d_in[4];
    const float* W2 = (const float*)d_in[5];
    const float* b2 = (const float*)d_in[6];
    float* out = (float*)d_out;

    const int M = in_sizes[0] / DIN;   // 32768 rows

    cudaFuncSetAttribute(fused_mlp_kernel,
                         cudaFuncAttributeMaxDynamicSharedMemorySize, SMEM_BYTES);
    fused_mlp_kernel<<<M / BM, 256, SMEM_BYTES>>>(x, W0, b0, W1, b1, W2, b2, out);
}

// round 5
// speedup vs baseline: 3.8629x; 3.8629x over previous
#include <cuda_runtime.h>
#include <cuda_bf16.h>
#include <cstdint>

#define DIN 1024
#define HD  128
#define BM  128
#define KC  64
#define NCHUNK (DIN/KC)   // 16

// ---------------- preconverted weights (transposed + bf16 hi/lo split) -----
__device__ __nv_bfloat16 g_W0T_hi[HD*DIN];
__device__ __nv_bfloat16 g_W0T_lo[HD*DIN];
__device__ __nv_bfloat16 g_W1T_hi[HD*HD];
__device__ __nv_bfloat16 g_W1T_lo[HD*HD];
__device__ __nv_bfloat16 g_W2T_hi[HD*HD];
__device__ __nv_bfloat16 g_W2T_lo[HD*HD];

// WT[n][k] = W[k][n]; hi = bf16(w), lo = bf16(w - hi)
__global__ void prep_w(const float* __restrict__ W, int K, int which)
{
    __shared__ float t[32][33];
    __nv_bfloat16* hi = which==0 ? g_W0T_hi : (which==1 ? g_W1T_hi : g_W2T_hi);
    __nv_bfloat16* lo = which==0 ? g_W0T_lo : (which==1 ? g_W1T_lo : g_W2T_lo);
    int bx = blockIdx.x, by = blockIdx.y;
    int tx = threadIdx.x, ty = threadIdx.y;   // (32,8)
    #pragma unroll
    for (int r = 0; r < 32; r += 8)
        t[ty+r][tx] = W[(size_t)(bx*32 + ty + r)*HD + by*32 + tx];
    __syncthreads();
    #pragma unroll
    for (int r = 0; r < 32; r += 8) {
        int n = by*32 + ty + r;
        int k = bx*32 + tx;
        float w = t[tx][ty+r];
        __nv_bfloat16 h = __float2bfloat16(w);
        hi[(size_t)n*K + k] = h;
        lo[(size_t)n*K + k] = __float2bfloat16(w - __bfloat162float(h));
    }
}

// ---------------- helpers ---------------------------------------------------
__device__ __forceinline__ uint32_t smem_u32(const void* p) {
    uint32_t a;
    asm("{ .reg .u64 t; cvta.to.shared.u64 t, %1; cvt.u32.u64 %0, t; }" : "=r"(a) : "l"(p));
    return a;
}
// swizzle for 128-byte rows (bits[9:7] -> XOR bits[6:4])
__device__ __forceinline__ uint32_t sw128(uint32_t o) { return o ^ ((o >> 3) & 0x70); }
// swizzle for 256-byte rows (bits[10:8] -> XOR bits[6:4])
__device__ __forceinline__ uint32_t sw256(uint32_t o) { return o ^ ((o >> 4) & 0x70); }

__device__ __forceinline__ void cpasync16(uint32_t dst, const void* src) {
    asm volatile("cp.async.cg.shared.global [%0], [%1], 16;" :: "r"(dst), "l"(src));
}
#define CP_COMMIT()  asm volatile("cp.async.commit_group;" ::: "memory")
#define CP_WAIT0()   asm volatile("cp.async.wait_group 0;"  ::: "memory")

__device__ __forceinline__ void ldsm4(uint32_t addr, uint32_t* r) {
    asm volatile("ldmatrix.sync.aligned.m8n8.x4.shared.b16 {%0,%1,%2,%3}, [%4];"
        : "=r"(r[0]), "=r"(r[1]), "=r"(r[2]), "=r"(r[3]) : "r"(addr));
}
__device__ __forceinline__ void mma16816(float* c, const uint32_t* a, uint32_t b0, uint32_t b1) {
    asm volatile("mma.sync.aligned.m16n8k16.row.col.f32.bf16.bf16.f32 "
        "{%0,%1,%2,%3}, {%4,%5,%6,%7}, {%8,%9}, {%0,%1,%2,%3};"
        : "+f"(c[0]), "+f"(c[1]), "+f"(c[2]), "+f"(c[3])
        : "r"(a[0]), "r"(a[1]), "r"(a[2]), "r"(a[3]), "r"(b0), "r"(b1));
}

// ---------------- smem layout ----------------------------------------------
// Regions R0/R1/R2, 64KB each.
// GEMM0: R0 = stage0, R1 = stage1. Stage: A_hi|A_lo|B_hi|B_lo (16KB each),
//        A rows 128B (64 bf16), B rows 128B ([n][k] K-major).
// After GEMM0: R0 = h_hi|h_lo (rows 256B), R1 = W1 hi|lo, R2 = W2 hi|lo.
#define STG    65536
#define A_HI   0
#define A_LO   16384
#define B_HI   32768
#define B_LO   49152
#define RG0    0
#define RG1    65536
#define RG2    131072
#define H_HI   0
#define H_LO   32768
#define S_BIAS 196608
#define SMEM_TOTAL (196608 + 1536)

__global__ __launch_bounds__(256)
void fused_mlp_mma(const float* __restrict__ x,
                   const float* __restrict__ b0,
                   const float* __restrict__ b1,
                   const float* __restrict__ b2,
                   float* __restrict__ out)
{
    extern __shared__ char smem[];
    const uint32_t su = smem_u32(smem);
    const int tid  = threadIdx.x;
    const int lane = tid & 31;
    const int wid  = tid >> 5;           // 8 warps
    const int mrow = wid * 16;           // warp's row group
    const int m0   = blockIdx.x * BM;

    float* b0s = (float*)(smem + S_BIAS);
    float* b1s = (float*)(smem + S_BIAS + 512);
    float* b2s = (float*)(smem + S_BIAS + 1024);
    if (tid < HD) { b0s[tid] = b0[tid]; b1s[tid] = b1[tid]; b2s[tid] = b2[tid]; }

    // ldmatrix lane addressing (within tiles)
    const uint32_t aRow    = (uint32_t)(mrow + (lane & 15));
    const uint32_t aColSel = (uint32_t)((lane >> 4) * 16);
    const uint32_t bRow    = (uint32_t)((lane & 7) + ((lane >> 4) & 1) * 8);
    const uint32_t bColSel = (uint32_t)(((lane >> 3) & 1) * 16);
    const int colbase = (lane & 3) * 2;

    // ---- loaders ----
    float4 xr[8];
    auto load_x = [&](int chunk) {
        const float* xb = x + (size_t)m0 * DIN + chunk * KC;
        #pragma unroll
        for (int j = 0; j < 8; j++) {
            int flat = j * 256 + tid;        // 0..2047
            int row = flat >> 4, c4 = flat & 15;
            xr[j] = *(const float4*)(xb + (size_t)row * DIN + c4 * 4);
        }
    };
    auto sts_A = [&](uint32_t stage_base) {
        #pragma unroll
        for (int j = 0; j < 8; j++) {
            int flat = j * 256 + tid;
            int row = flat >> 4, c4 = flat & 15;
            float4 f = xr[j];
            __nv_bfloat162 h01 = __floats2bfloat162_rn(f.x, f.y);
            __nv_bfloat162 h23 = __floats2bfloat162_rn(f.z, f.w);
            __nv_bfloat162 l01 = __floats2bfloat162_rn(f.x - __low2float(h01), f.y - __high2float(h01));
            __nv_bfloat162 l23 = __floats2bfloat162_rn(f.z - __low2float(h23), f.w - __high2float(h23));
            uint32_t off = sw128((uint32_t)(row * 128 + c4 * 8));
            uint2 hv = { *(uint32_t*)&h01, *(uint32_t*)&h23 };
            uint2 lv = { *(uint32_t*)&l01, *(uint32_t*)&l23 };
            *(uint2*)(smem + stage_base + A_HI + off) = hv;
            *(uint2*)(smem + stage_base + A_LO + off) = lv;
        }
    };
    auto cp_B = [&](int chunk, uint32_t stage_base) {
        const int k0 = chunk * KC;
        #pragma unroll
        for (int j = 0; j < 4; j++) {
            int flat = j * 256 + tid;        // 0..1023
            int row = flat >> 3, c8 = flat & 7;
            uint32_t off = sw128((uint32_t)(row * 128 + c8 * 16));
            cpasync16(su + stage_base + B_HI + off, g_W0T_hi + (size_t)row * DIN + k0 + c8 * 8);
            cpasync16(su + stage_base + B_LO + off, g_W0T_lo + (size_t)row * DIN + k0 + c8 * 8);
        }
    };

    float acc[16][4];
    #pragma unroll
    for (int n = 0; n < 16; n++)
        #pragma unroll
        for (int q = 0; q < 4; q++) acc[n][q] = 0.f;

    // ---- GEMM0 mainloop: 2-stage ring --------------------------------------
    load_x(0);
    cp_B(0, RG0); CP_COMMIT();
    sts_A(RG0);
    load_x(1);
    CP_WAIT0();
    __syncthreads();

    for (int i = 0; i < NCHUNK; i++) {
        const uint32_t sb  = (i & 1) ? RG1 : RG0;
        const uint32_t sbn = (i & 1) ? RG0 : RG1;
        if (i < NCHUNK - 1) {
            cp_B(i + 1, sbn); CP_COMMIT();
            sts_A(sbn);                     // xr holds chunk i+1
            if (i < NCHUNK - 2) load_x(i + 2);
        }
        // compute chunk i from stage sb (3-pass bf16)
        #pragma unroll
        for (int ks = 0; ks < 4; ks++) {
            uint32_t ah[4], al[4];
            uint32_t aoff = sw128(aRow * 128 + (uint32_t)ks * 32 + aColSel);
            ldsm4(su + sb + A_HI + aoff, ah);
            ldsm4(su + sb + A_LO + aoff, al);
            #pragma unroll
            for (int np = 0; np < 8; np++) {
                uint32_t bh[4], bl[4];
                uint32_t boff = sw128(((uint32_t)np * 16 + bRow) * 128 + (uint32_t)ks * 32 + bColSel);
                ldsm4(su + sb + B_HI + boff, bh);
                ldsm4(su + sb + B_LO + boff, bl);
                mma16816(acc[np*2],   ah, bh[0], bh[1]);
                mma16816(acc[np*2],   ah, bl[0], bl[1]);
                mma16816(acc[np*2],   al, bh[0], bh[1]);
                mma16816(acc[np*2+1], ah, bh[2], bh[3]);
                mma16816(acc[np*2+1], ah, bl[2], bl[3]);
                mma16816(acc[np*2+1], al, bh[2], bh[3]);
            }
        }
        if (i < NCHUNK - 1) {
            CP_WAIT0();
            __syncthreads();
        }
    }
    __syncthreads();   // all warps done with both stages

    // ---- prefetch W1/W2 into R1/R2 (overlap with rmsnorm epilogue) --------
    {
        auto cp_W = [&](const __nv_bfloat16* src, uint32_t base) {
            #pragma unroll
            for (int j = 0; j < 8; j++) {
                int flat = j * 256 + tid;    // 0..2047
                int row = flat >> 4, c16 = flat & 15;
                uint32_t off = sw256((uint32_t)(row * 256 + c16 * 16));
                cpasync16(su + base + off, src + (size_t)row * HD + c16 * 8);
            }
        };
        cp_W(g_W1T_hi, RG1 + H_HI);
        cp_W(g_W1T_lo, RG1 + H_LO);
        cp_W(g_W2T_hi, RG2 + H_HI);
        cp_W(g_W2T_lo, RG2 + H_LO);
        CP_COMMIT();
    }

    // ---- epilogue 0: bias + rmsnorm; h -> regs + smem (bf16 hi/lo) --------
    const int r0 = mrow + (lane >> 2);
    const int r1 = r0 + 8;
    float hn[64];    // [0..31]: row r0 cols; [32..63]: row r1 cols
    {
        float ss0 = 0.f, ss1 = 0.f;
        #pragma unroll
        for (int nt = 0; nt < 16; nt++) {
            float2 bv = *(float2*)&b0s[nt*8 + colbase];
            float v0 = acc[nt][0] + bv.x;
            float v1 = acc[nt][1] + bv.y;
            float v2 = acc[nt][2] + bv.x;
            float v3 = acc[nt][3] + bv.y;
            hn[nt*2] = v0; hn[nt*2+1] = v1; hn[32+nt*2] = v2; hn[32+nt*2+1] = v3;
            ss0 = fmaf(v0, v0, fmaf(v1, v1, ss0));
            ss1 = fmaf(v2, v2, fmaf(v3, v3, ss1));
        }
        ss0 += __shfl_xor_sync(0xffffffffu, ss0, 1);
        ss0 += __shfl_xor_sync(0xffffffffu, ss0, 2);
        ss1 += __shfl_xor_sync(0xffffffffu, ss1, 1);
        ss1 += __shfl_xor_sync(0xffffffffu, ss1, 2);
        float sc0 = rsqrtf(ss0 * (1.f/128.f) + 1e-6f);
        float sc1 = rsqrtf(ss1 * (1.f/128.f) + 1e-6f);
        #pragma unroll
        for (int nt = 0; nt < 16; nt++) {
            float v0 = hn[nt*2]      * sc0;
            float v1 = hn[nt*2+1]    * sc0;
            float v2 = hn[32+nt*2]   * sc1;
            float v3 = hn[32+nt*2+1] * sc1;
            hn[nt*2] = v0; hn[nt*2+1] = v1; hn[32+nt*2] = v2; hn[32+nt*2+1] = v3;
            __nv_bfloat162 h01 = __floats2bfloat162_rn(v0, v1);
            __nv_bfloat162 h23 = __floats2bfloat162_rn(v2, v3);
            __nv_bfloat162 l01 = __floats2bfloat162_rn(v0 - __low2float(h01), v1 - __high2float(h01));
            __nv_bfloat162 l23 = __floats2bfloat162_rn(v2 - __low2float(h23), v3 - __high2float(h23));
            uint32_t o0 = sw256((uint32_t)(r0 * 256 + (nt*8 + colbase) * 2));
            uint32_t o1 = sw256((uint32_t)(r1 * 256 + (nt*8 + colbase) * 2));
            *(uint32_t*)(smem + RG0 + H_HI + o0) = *(uint32_t*)&h01;
            *(uint32_t*)(smem + RG0 + H_LO + o0) = *(uint32_t*)&l01;
            *(uint32_t*)(smem + RG0 + H_HI + o1) = *(uint32_t*)&h23;
            *(uint32_t*)(smem + RG0 + H_LO + o1) = *(uint32_t*)&l23;
        }
    }
    CP_WAIT0();
    __syncthreads();

    // ---- GEMM1: acc = h @ W1 (3-pass, K=128) ------------------------------
    #pragma unroll
    for (int n = 0; n < 16; n++)
        #pragma unroll
        for (int q = 0; q < 4; q++) acc[n][q] = 0.f;

    #pragma unroll
    for (int ks = 0; ks < 8; ks++) {
        uint32_t ah[4], al[4];
        uint32_t aoff = sw256(aRow * 256 + (uint32_t)ks * 32 + aColSel);
        ldsm4(su + RG0 + H_HI + aoff, ah);
        ldsm4(su + RG0 + H_LO + aoff, al);
        #pragma unroll
        for (int np = 0; np < 8; np++) {
            uint32_t bh[4], bl[4];
            uint32_t boff = sw256(((uint32_t)np * 16 + bRow) * 256 + (uint32_t)ks * 32 + bColSel);
            ldsm4(su + RG1 + H_HI + boff, bh);
            ldsm4(su + RG1 + H_LO + boff, bl);
            mma16816(acc[np*2],   ah, bh[0], bh[1]);
            mma16816(acc[np*2],   ah, bl[0], bl[1]);
            mma16816(acc[np*2],   al, bh[0], bh[1]);
            mma16816(acc[np*2+1], ah, bh[2], bh[3]);
            mma16816(acc[np*2+1], ah, bl[2], bl[3]);
            mma16816(acc[np*2+1], al, bh[2], bh[3]);
        }
    }
    __syncthreads();   // everyone done reading h before overwrite

    // ---- epilogue 1: sigmoid + residual; h1 -> regs + smem ----------------
    #pragma unroll
    for (int nt = 0; nt < 16; nt++) {
        float2 bv = *(float2*)&b1s[nt*8 + colbase];
        float z0 = acc[nt][0] + bv.x;
        float z1 = acc[nt][1] + bv.y;
        float z2 = acc[nt][2] + bv.x;
        float z3 = acc[nt][3] + bv.y;
        float v0 = 1.f / (1.f + __expf(-z0)) + hn[nt*2];
        float v1 = 1.f / (1.f + __expf(-z1)) + hn[nt*2+1];
        float v2 = 1.f / (1.f + __expf(-z2)) + hn[32+nt*2];
        float v3 = 1.f / (1.f + __expf(-z3)) + hn[32+nt*2+1];
        hn[nt*2] = v0; hn[nt*2+1] = v1; hn[32+nt*2] = v2; hn[32+nt*2+1] = v3;
        __nv_bfloat162 h01 = __floats2bfloat162_rn(v0, v1);
        __nv_bfloat162 h23 = __floats2bfloat162_rn(v2, v3);
        __nv_bfloat162 l01 = __floats2bfloat162_rn(v0 - __low2float(h01), v1 - __high2float(h01));
        __nv_bfloat162 l23 = __floats2bfloat162_rn(v2 - __low2float(h23), v3 - __high2float(h23));
        uint32_t o0 = sw256((uint32_t)(r0 * 256 + (nt*8 + colbase) * 2));
        uint32_t o1 = sw256((uint32_t)(r1 * 256 + (nt*8 + colbase) * 2));
        *(uint32_t*)(smem + RG0 + H_HI + o0) = *(uint32_t*)&h01;
        *(uint32_t*)(smem + RG0 + H_LO + o0) = *(uint32_t*)&l01;
        *(uint32_t*)(smem + RG0 + H_HI + o1) = *(uint32_t*)&h23;
        *(uint32_t*)(smem + RG0 + H_LO + o1) = *(uint32_t*)&l23;
    }
    __syncthreads();

    // ---- GEMM2: acc = h1 @ W2 (3-pass, K=128) -----------------------------
    #pragma unroll
    for (int n = 0; n < 16; n++)
        #pragma unroll
        for (int q = 0; q < 4; q++) acc[n][q] = 0.f;

    #pragma unroll
    for (int ks = 0; ks < 8; ks++) {
        uint32_t ah[4], al[4];
        uint32_t aoff = sw256(aRow * 256 + (uint32_t)ks * 32 + aColSel);
        ldsm4(su + RG0 + H_HI + aoff, ah);
        ldsm4(su + RG0 + H_LO + aoff, al);
        #pragma unroll
        for (int np = 0; np < 8; np++) {
            uint32_t bh[4], bl[4];
            uint32_t boff = sw256(((uint32_t)np * 16 + bRow) * 256 + (uint32_t)ks * 32 + bColSel);
            ldsm4(su + RG2 + H_HI + boff, bh);
            ldsm4(su + RG2 + H_LO + boff, bl);
            mma16816(acc[np*2],   ah, bh[0], bh[1]);
            mma16816(acc[np*2],   ah, bl[0], bl[1]);
            mma16816(acc[np*2],   al, bh[0], bh[1]);
            mma16816(acc[np*2+1], ah, bh[2], bh[3]);
            mma16816(acc[np*2+1], ah, bl[2], bl[3]);
            mma16816(acc[np*2+1], al, bh[2], bh[3]);
        }
    }

    // ---- epilogue 2: relu + residual; store -------------------------------
    float* orow0 = out + (size_t)(m0 + r0) * HD;
    float* orow1 = out + (size_t)(m0 + r1) * HD;
    #pragma unroll
    for (int nt = 0; nt < 16; nt++) {
        float2 bv = *(float2*)&b2s[nt*8 + colbase];
        float2 o0, o1;
        o0.x = fmaxf(acc[nt][0] + bv.x, 0.f) + hn[nt*2];
        o0.y = fmaxf(acc[nt][1] + bv.y, 0.f) + hn[nt*2+1];
        o1.x = fmaxf(acc[nt][2] + bv.x, 0.f) + hn[32+nt*2];
        o1.y = fmaxf(acc[nt][3] + bv.y, 0.f) + hn[32+nt*2+1];
        *(float2*)(orow0 + nt*8 + colbase) = o0;
        *(float2*)(orow1 + nt*8 + colbase) = o1;
    }
}

// ---------------- launch ----------------------------------------------------
extern "C" void kernel_launch(void* const* d_in, const int* in_sizes, int n_in,
                              void* d_out, int out_size)
{
    const float* x  = (const float*)d_in[0];
    const float* W0 = (const float*)d_in[1];
    const float* b0 = (const float*)d_in[2];
    const float* W1 = (const float*)d_in[3];
    const float* b1 = (const float*)d_in[4];
    const float* W2 = (const float*)d_in[5];
    const float* b2 = (const float*)d_in[6];
    float* out = (float*)d_out;

    const int M = in_sizes[0] / DIN;   // 32768

    prep_w<<<dim3(DIN/32, HD/32), dim3(32, 8)>>>(W0, DIN, 0);
    prep_w<<<dim3(HD/32,  HD/32), dim3(32, 8)>>>(W1, HD, 1);
    prep_w<<<dim3(HD/32,  HD/32), dim3(32, 8)>>>(W2, HD, 2);

    cudaFuncSetAttribute(fused_mlp_mma,
                         cudaFuncAttributeMaxDynamicSharedMemorySize, SMEM_TOTAL);
    fused_mlp_mma<<<M / BM, 256, SMEM_TOTAL>>>(x, b0, b1, b2, out);
}